// round 1
// baseline (speedup 1.0000x reference)
#include <cuda_runtime.h>

#define HC    128      // H*C
#define HEADS 4
#define CC    32
#define NEG   0.2f
#define NMAX  100000
#define EMAX  1600000

// ---------------- scratch (no allocation allowed) ----------------
__device__ float g_h[NMAX * HC];          // projected features [N,128]
__device__ float g_asrc[NMAX * HEADS];    // per-node src attention dot [N,4]
__device__ float g_adst[NMAX * HEADS];    // per-node dst attention dot [N,4]
__device__ int   g_deg[NMAX];
__device__ int   g_offs[NMAX + 1];
__device__ int   g_cursor[NMAX];
__device__ int   g_csr[EMAX];             // src indices sorted by dst
__device__ int   g_part[128];
__device__ int   g_base[128];

// ---------------- K1: h = x @ W, fused a_src/a_dst ----------------
// 256 threads/block, 32 rows/block, each thread: 4 rows x 4 cols.
__global__ void k_proj(const float* __restrict__ x, const float* __restrict__ W,
                       const float* __restrict__ att_s, const float* __restrict__ att_d,
                       int n)
{
    extern __shared__ float sm[];
    float* Ws = sm;                  // 128*128 floats = 64KB
    float* xs = sm + 128 * 128;      // 32*128 floats = 16KB

    int t = threadIdx.x;
    const float4* W4 = (const float4*)W;
    float4* Ws4 = (float4*)Ws;
    #pragma unroll
    for (int i = t; i < 4096; i += 256) Ws4[i] = W4[i];

    int row0 = blockIdx.x * 32;
    float4* xs4 = (float4*)xs;
    const float4* xg4 = (const float4*)(x + (size_t)row0 * HC);
    #pragma unroll
    for (int i = t; i < 1024; i += 256) xs4[i] = xg4[i];
    __syncthreads();

    int cg = t & 31;        // column group -> cols j0..j0+3
    int rg = t >> 5;        // row group (warp id) -> rows rg*4..rg*4+3
    int j0 = cg * 4;

    float4 a0 = make_float4(0.f,0.f,0.f,0.f);
    float4 a1 = a0, a2 = a0, a3 = a0;
    const float* xr = xs + rg * 4 * HC;

    #pragma unroll 4
    for (int k = 0; k < 128; k++) {
        float4 w = Ws4[k * 32 + cg];
        float x0 = xr[k];
        float x1 = xr[k + 128];
        float x2 = xr[k + 256];
        float x3 = xr[k + 384];
        a0.x += w.x * x0; a0.y += w.y * x0; a0.z += w.z * x0; a0.w += w.w * x0;
        a1.x += w.x * x1; a1.y += w.y * x1; a1.z += w.z * x1; a1.w += w.w * x1;
        a2.x += w.x * x2; a2.y += w.y * x2; a2.z += w.z * x2; a2.w += w.w * x2;
        a3.x += w.x * x3; a3.y += w.y * x3; a3.z += w.z * x3; a3.w += w.w * x3;
    }

    float4* h4 = (float4*)g_h;
    int r0 = row0 + rg * 4;
    h4[(size_t)(r0 + 0) * 32 + cg] = a0;
    h4[(size_t)(r0 + 1) * 32 + cg] = a1;
    h4[(size_t)(r0 + 2) * 32 + cg] = a2;
    h4[(size_t)(r0 + 3) * 32 + cg] = a3;

    // attention dots: att flattened [H*C] matches j layout exactly
    float4 avs = ((const float4*)att_s)[cg];
    float4 avd = ((const float4*)att_d)[cg];
    float ps[4], pd[4];
    ps[0] = a0.x*avs.x + a0.y*avs.y + a0.z*avs.z + a0.w*avs.w;
    ps[1] = a1.x*avs.x + a1.y*avs.y + a1.z*avs.z + a1.w*avs.w;
    ps[2] = a2.x*avs.x + a2.y*avs.y + a2.z*avs.z + a2.w*avs.w;
    ps[3] = a3.x*avs.x + a3.y*avs.y + a3.z*avs.z + a3.w*avs.w;
    pd[0] = a0.x*avd.x + a0.y*avd.y + a0.z*avd.z + a0.w*avd.w;
    pd[1] = a1.x*avd.x + a1.y*avd.y + a1.z*avd.z + a1.w*avd.w;
    pd[2] = a2.x*avd.x + a2.y*avd.y + a2.z*avd.z + a2.w*avd.w;
    pd[3] = a3.x*avd.x + a3.y*avd.y + a3.z*avd.z + a3.w*avd.w;
    #pragma unroll
    for (int off = 4; off >= 1; off >>= 1) {
        #pragma unroll
        for (int i = 0; i < 4; i++) {
            ps[i] += __shfl_xor_sync(0xffffffffu, ps[i], off);
            pd[i] += __shfl_xor_sync(0xffffffffu, pd[i], off);
        }
    }
    int head = cg >> 3;
    if ((cg & 7) == 0) {
        #pragma unroll
        for (int i = 0; i < 4; i++) {
            g_asrc[(r0 + i) * HEADS + head] = ps[i];
            g_adst[(r0 + i) * HEADS + head] = pd[i];
        }
    }
    (void)j0;
}

// ---------------- CSR build ----------------
__global__ void k_zero(int n) {
    int i = blockIdx.x * blockDim.x + threadIdx.x;
    if (i < n) g_deg[i] = 0;
}

__global__ void k_count(const int* __restrict__ ei, int e) {
    int i = blockIdx.x * blockDim.x + threadIdx.x;
    if (i < e) atomicAdd(&g_deg[ei[e + i]], 1);
}

__global__ void k_scan1(int n) {
    __shared__ int s[1024];
    int tid = threadIdx.x;
    int i = blockIdx.x * 1024 + tid;
    int v = (i < n) ? g_deg[i] : 0;
    s[tid] = v;
    __syncthreads();
    #pragma unroll
    for (int off = 1; off < 1024; off <<= 1) {
        int t2 = (tid >= off) ? s[tid - off] : 0;
        __syncthreads();
        s[tid] += t2;
        __syncthreads();
    }
    if (i < n) g_offs[i] = s[tid] - v;          // exclusive within chunk
    if (tid == 1023) g_part[blockIdx.x] = s[1023];
}

__global__ void k_scan2(int nchunks, int n) {
    if (threadIdx.x == 0 && blockIdx.x == 0) {
        int run = 0;
        for (int c = 0; c < nchunks; c++) { g_base[c] = run; run += g_part[c]; }
        g_offs[n] = run;
    }
}

__global__ void k_scan3(int n) {
    int i = blockIdx.x * 1024 + threadIdx.x;
    if (i < n) {
        int v = g_offs[i] + g_base[blockIdx.x];
        g_offs[i] = v;
        g_cursor[i] = v;
    }
}

__global__ void k_scatter(const int* __restrict__ ei, int e) {
    int i = blockIdx.x * blockDim.x + threadIdx.x;
    if (i < e) {
        int dst = ei[e + i];
        int pos = atomicAdd(&g_cursor[dst], 1);
        g_csr[pos] = ei[i];
    }
}

// ---------------- K main: one warp per dst node, online softmax ----------------
__global__ void k_main(const float* __restrict__ bias, float* __restrict__ out, int n)
{
    int node = (blockIdx.x * blockDim.x + threadIdx.x) >> 5;
    if (node >= n) return;
    int lane = threadIdx.x & 31;
    int head = lane >> 3;                 // lane covers cols lane*4..lane*4+3, all in one head

    float adst = g_adst[node * HEADS + head];
    float m = -1e30f, s = 0.f;
    float4 acc = make_float4(0.f,0.f,0.f,0.f);

    int beg = g_offs[node];
    int end = g_offs[node + 1];
    const float4* h4 = (const float4*)g_h;

    for (int i = beg; i <= end; i++) {    // i==end -> self loop
        int src = (i == end) ? node : g_csr[i];
        float e = g_asrc[src * HEADS + head] + adst;
        e = (e > 0.f) ? e : NEG * e;
        float4 hv = h4[(size_t)src * 32 + lane];
        float mn = fmaxf(m, e);
        float sc = __expf(m - mn);
        float p  = __expf(e - mn);
        s = s * sc + p;
        acc.x = acc.x * sc + p * hv.x;
        acc.y = acc.y * sc + p * hv.y;
        acc.z = acc.z * sc + p * hv.z;
        acc.w = acc.w * sc + p * hv.w;
        m = mn;
    }

    float inv = 1.f / (s + 1e-16f);
    acc.x *= inv; acc.y *= inv; acc.z *= inv; acc.w *= inv;

    // mean over heads: lanes differing by 8/16 hold same c, different head
    #pragma unroll
    for (int off = 8; off <= 16; off <<= 1) {
        acc.x += __shfl_xor_sync(0xffffffffu, acc.x, off);
        acc.y += __shfl_xor_sync(0xffffffffu, acc.y, off);
        acc.z += __shfl_xor_sync(0xffffffffu, acc.z, off);
        acc.w += __shfl_xor_sync(0xffffffffu, acc.w, off);
    }

    if (lane < 8) {
        float4 b = ((const float4*)bias)[lane];
        float4 o;
        o.x = fmaxf(acc.x * 0.25f + b.x, 0.f);
        o.y = fmaxf(acc.y * 0.25f + b.y, 0.f);
        o.z = fmaxf(acc.z * 0.25f + b.z, 0.f);
        o.w = fmaxf(acc.w * 0.25f + b.w, 0.f);
        ((float4*)out)[(size_t)node * 8 + lane] = o;
    }
}

// ---------------- launch ----------------
extern "C" void kernel_launch(void* const* d_in, const int* in_sizes, int n_in,
                              void* d_out, int out_size)
{
    const float* x     = (const float*)d_in[0];
    const int*   ei    = (const int*)d_in[1];
    const float* W     = (const float*)d_in[2];
    const float* att_s = (const float*)d_in[3];
    const float* att_d = (const float*)d_in[4];
    const float* bias  = (const float*)d_in[5];
    float* out = (float*)d_out;

    int n = in_sizes[0] / HC;   // 100000
    int e = in_sizes[1] / 2;    // 1600000

    cudaFuncSetAttribute(k_proj, cudaFuncAttributeMaxDynamicSharedMemorySize, 81920);

    k_proj<<<(n + 31) / 32, 256, 81920>>>(x, W, att_s, att_d, n);

    k_zero<<<(n + 255) / 256, 256>>>(n);
    k_count<<<(e + 255) / 256, 256>>>(ei, e);

    int nchunks = (n + 1023) / 1024;
    k_scan1<<<nchunks, 1024>>>(n);
    k_scan2<<<1, 32>>>(nchunks, n);
    k_scan3<<<nchunks, 1024>>>(n);
    k_scatter<<<(e + 255) / 256, 256>>>(ei, e);

    k_main<<<(n * 32 + 255) / 256, 256>>>(bias, out, n);
}

// round 2
// speedup vs baseline: 1.2015x; 1.2015x over previous
#include <cuda_runtime.h>

#define HC    128      // H*C
#define HEADS 4
#define NEG   0.2f
#define NMAX  100000
#define EMAX  1600000

typedef unsigned long long u64;

// ---------------- scratch (no allocation allowed) ----------------
__device__ float g_h[NMAX * HC];          // projected features [N,128]
__device__ float g_asrc[NMAX * HEADS];    // per-node src attention dot [N,4]
__device__ float g_adst[NMAX * HEADS];    // per-node dst attention dot [N,4]
__device__ int   g_deg[NMAX];
__device__ int   g_offs[NMAX + 1];
__device__ int   g_cursor[NMAX];
__device__ int   g_csr[EMAX];             // src indices grouped by dst
__device__ int   g_part[128];
__device__ int   g_base[128];

// ---------------- packed f32x2 helpers ----------------
__device__ __forceinline__ u64 ffma2(u64 a, u64 b, u64 c) {
    u64 d;
    asm("fma.rn.f32x2 %0, %1, %2, %3;" : "=l"(d) : "l"(a), "l"(b), "l"(c));
    return d;
}
__device__ __forceinline__ u64 dup2(float v) {
    u64 d; unsigned r = __float_as_uint(v);
    asm("mov.b64 %0, {%1, %1};" : "=l"(d) : "r"(r));
    return d;
}
__device__ __forceinline__ void unpack2(u64 v, float& lo, float& hi) {
    unsigned a, b;
    asm("mov.b64 {%0, %1}, %2;" : "=r"(a), "=r"(b) : "l"(v));
    lo = __uint_as_float(a); hi = __uint_as_float(b);
}

// ---------------- proj: 32 rows per block, f32x2 FFMA ----------------
__device__ __forceinline__ void proj_rows(int row0, const float* __restrict__ x,
        const float* __restrict__ W, const float* __restrict__ att_s,
        const float* __restrict__ att_d, float* sm)
{
    float* Ws = sm;                  // 128*128 floats = 64KB
    float* xs = sm + 128 * 128;      // 32*128 floats = 16KB
    int t = threadIdx.x;

    const float4* W4 = (const float4*)W;
    float4* Ws4 = (float4*)Ws;
    #pragma unroll
    for (int i = t; i < 4096; i += 256) Ws4[i] = W4[i];

    float4* xs4 = (float4*)xs;
    const float4* xg4 = (const float4*)(x + (size_t)row0 * HC);
    #pragma unroll
    for (int i = t; i < 1024; i += 256) xs4[i] = xg4[i];
    __syncthreads();

    int cg = t & 31;        // cols cg*4..cg*4+3 (two f32x2 pairs)
    int rg = t >> 5;        // rows rg*4..rg*4+3

    u64 A[4][2];
    #pragma unroll
    for (int r = 0; r < 4; r++) { A[r][0] = 0ull; A[r][1] = 0ull; }

    const u64* Ws2 = (const u64*)Ws;
    const float* xr = xs + rg * 4 * HC;

    #pragma unroll 4
    for (int k = 0; k < 128; k++) {
        u64 wl = Ws2[(k * 32 + cg) * 2];
        u64 wh = Ws2[(k * 32 + cg) * 2 + 1];
        u64 x0 = dup2(xr[k]);
        u64 x1 = dup2(xr[k + 128]);
        u64 x2 = dup2(xr[k + 256]);
        u64 x3 = dup2(xr[k + 384]);
        A[0][0] = ffma2(wl, x0, A[0][0]); A[0][1] = ffma2(wh, x0, A[0][1]);
        A[1][0] = ffma2(wl, x1, A[1][0]); A[1][1] = ffma2(wh, x1, A[1][1]);
        A[2][0] = ffma2(wl, x2, A[2][0]); A[2][1] = ffma2(wh, x2, A[2][1]);
        A[3][0] = ffma2(wl, x3, A[3][0]); A[3][1] = ffma2(wh, x3, A[3][1]);
    }

    // unpack, store h, compute attention dots
    float4 av[4];
    float4 avs = ((const float4*)att_s)[cg];
    float4 avd = ((const float4*)att_d)[cg];
    float ps[4], pd[4];
    float4* h4 = (float4*)g_h;
    int r0 = row0 + rg * 4;

    #pragma unroll
    for (int r = 0; r < 4; r++) {
        float4 a;
        unpack2(A[r][0], a.x, a.y);
        unpack2(A[r][1], a.z, a.w);
        h4[(size_t)(r0 + r) * 32 + cg] = a;
        ps[r] = a.x*avs.x + a.y*avs.y + a.z*avs.z + a.w*avs.w;
        pd[r] = a.x*avd.x + a.y*avd.y + a.z*avd.z + a.w*avd.w;
        av[r] = a;
    }
    (void)av;

    #pragma unroll
    for (int off = 4; off >= 1; off >>= 1) {
        #pragma unroll
        for (int i = 0; i < 4; i++) {
            ps[i] += __shfl_xor_sync(0xffffffffu, ps[i], off);
            pd[i] += __shfl_xor_sync(0xffffffffu, pd[i], off);
        }
    }
    int head = cg >> 3;
    if ((cg & 7) == 0) {
        #pragma unroll
        for (int i = 0; i < 4; i++) {
            g_asrc[(r0 + i) * HEADS + head] = ps[i];
            g_adst[(r0 + i) * HEADS + head] = pd[i];
        }
    }
}

// ---------------- phase A: aux blocks count, rest project ----------------
__global__ void __launch_bounds__(256) k_pA(const float* __restrict__ x,
        const float* __restrict__ W, const float* __restrict__ att_s,
        const float* __restrict__ att_d, const int* __restrict__ ei,
        int e, int aux)
{
    extern __shared__ float sm[];
    if ((int)blockIdx.x < aux) {
        const int4* d4 = (const int4*)(ei + e);
        int nt = aux * 256;
        int e4 = e >> 2;
        for (int i = blockIdx.x * 256 + threadIdx.x; i < e4; i += nt) {
            int4 v = d4[i];
            atomicAdd(&g_deg[v.x], 1);
            atomicAdd(&g_deg[v.y], 1);
            atomicAdd(&g_deg[v.z], 1);
            atomicAdd(&g_deg[v.w], 1);
        }
        return;
    }
    proj_rows((blockIdx.x - aux) * 32, x, W, att_s, att_d, sm);
}

// ---------------- phase B: aux blocks scatter, rest project ----------------
__global__ void __launch_bounds__(256) k_pB(const float* __restrict__ x,
        const float* __restrict__ W, const float* __restrict__ att_s,
        const float* __restrict__ att_d, const int* __restrict__ ei,
        int e, int aux, int rowBase)
{
    extern __shared__ float sm[];
    if ((int)blockIdx.x < aux) {
        const int4* s4 = (const int4*)ei;
        const int4* d4 = (const int4*)(ei + e);
        int nt = aux * 256;
        int e4 = e >> 2;
        for (int i = blockIdx.x * 256 + threadIdx.x; i < e4; i += nt) {
            int4 sv = s4[i];
            int4 dv = d4[i];
            g_csr[atomicAdd(&g_cursor[dv.x], 1)] = sv.x;
            g_csr[atomicAdd(&g_cursor[dv.y], 1)] = sv.y;
            g_csr[atomicAdd(&g_cursor[dv.z], 1)] = sv.z;
            g_csr[atomicAdd(&g_cursor[dv.w], 1)] = sv.w;
        }
        return;
    }
    proj_rows(rowBase + (blockIdx.x - aux) * 32, x, W, att_s, att_d, sm);
}

// ---------------- CSR scan chain ----------------
__global__ void k_zero(int n) {
    int i = blockIdx.x * blockDim.x + threadIdx.x;
    if (i < n) g_deg[i] = 0;
}

__global__ void k_scan1(int n) {
    __shared__ int s[1024];
    int tid = threadIdx.x;
    int i = blockIdx.x * 1024 + tid;
    int v = (i < n) ? g_deg[i] : 0;
    s[tid] = v;
    __syncthreads();
    #pragma unroll
    for (int off = 1; off < 1024; off <<= 1) {
        int t2 = (tid >= off) ? s[tid - off] : 0;
        __syncthreads();
        s[tid] += t2;
        __syncthreads();
    }
    if (i < n) g_offs[i] = s[tid] - v;          // exclusive within chunk
    if (tid == 1023) g_part[blockIdx.x] = s[1023];
}

__global__ void k_scan2(int nchunks, int n) {
    __shared__ int s[128];
    int t = threadIdx.x;
    int v = (t < nchunks) ? g_part[t] : 0;
    s[t] = v;
    __syncthreads();
    #pragma unroll
    for (int off = 1; off < 128; off <<= 1) {
        int u = (t >= off) ? s[t - off] : 0;
        __syncthreads();
        s[t] += u;
        __syncthreads();
    }
    if (t < nchunks) g_base[t] = s[t] - v;      // exclusive
    if (t == nchunks - 1) g_offs[n] = s[t];     // total edges
}

__global__ void k_scan3(int n) {
    int i = blockIdx.x * 1024 + threadIdx.x;
    if (i < n) {
        int v = g_offs[i] + g_base[blockIdx.x];
        g_offs[i] = v;
        g_cursor[i] = v;
    }
}

// ---------------- main: one warp per dst node, no-max softmax, unroll 2 ----------------
__global__ void k_main(const float* __restrict__ bias, float* __restrict__ out, int n)
{
    int node = (blockIdx.x * blockDim.x + threadIdx.x) >> 5;
    if (node >= n) return;
    int lane = threadIdx.x & 31;
    int head = lane >> 3;

    float adst = g_adst[node * HEADS + head];
    float s = 0.f;
    float4 acc = make_float4(0.f, 0.f, 0.f, 0.f);

    int beg = g_offs[node];
    int end = g_offs[node + 1];
    const float4* h4 = (const float4*)g_h;

    int i = beg;
    for (; i + 2 <= end; i += 2) {
        int s0 = g_csr[i];
        int s1 = g_csr[i + 1];
        float e0 = g_asrc[s0 * HEADS + head] + adst;
        float e1 = g_asrc[s1 * HEADS + head] + adst;
        e0 = (e0 > 0.f) ? e0 : NEG * e0;
        e1 = (e1 > 0.f) ? e1 : NEG * e1;
        float4 h0 = h4[(size_t)s0 * 32 + lane];
        float4 h1 = h4[(size_t)s1 * 32 + lane];
        float p0 = __expf(e0);
        float p1 = __expf(e1);
        s += p0 + p1;
        acc.x = fmaf(p0, h0.x, fmaf(p1, h1.x, acc.x));
        acc.y = fmaf(p0, h0.y, fmaf(p1, h1.y, acc.y));
        acc.z = fmaf(p0, h0.z, fmaf(p1, h1.z, acc.z));
        acc.w = fmaf(p0, h0.w, fmaf(p1, h1.w, acc.w));
    }
    if (i < end) {
        int s0 = g_csr[i];
        float e0 = g_asrc[s0 * HEADS + head] + adst;
        e0 = (e0 > 0.f) ? e0 : NEG * e0;
        float4 h0 = h4[(size_t)s0 * 32 + lane];
        float p0 = __expf(e0);
        s += p0;
        acc.x = fmaf(p0, h0.x, acc.x);
        acc.y = fmaf(p0, h0.y, acc.y);
        acc.z = fmaf(p0, h0.z, acc.z);
        acc.w = fmaf(p0, h0.w, acc.w);
    }
    // self loop
    {
        float e0 = g_asrc[node * HEADS + head] + adst;
        e0 = (e0 > 0.f) ? e0 : NEG * e0;
        float4 h0 = h4[(size_t)node * 32 + lane];
        float p0 = __expf(e0);
        s += p0;
        acc.x = fmaf(p0, h0.x, acc.x);
        acc.y = fmaf(p0, h0.y, acc.y);
        acc.z = fmaf(p0, h0.z, acc.z);
        acc.w = fmaf(p0, h0.w, acc.w);
    }

    float inv = 1.f / (s + 1e-16f);
    acc.x *= inv; acc.y *= inv; acc.z *= inv; acc.w *= inv;

    // mean over heads: lanes differing by 8/16 hold same c, different head
    #pragma unroll
    for (int off = 8; off <= 16; off <<= 1) {
        acc.x += __shfl_xor_sync(0xffffffffu, acc.x, off);
        acc.y += __shfl_xor_sync(0xffffffffu, acc.y, off);
        acc.z += __shfl_xor_sync(0xffffffffu, acc.z, off);
        acc.w += __shfl_xor_sync(0xffffffffu, acc.w, off);
    }

    if (lane < 8) {
        float4 b = ((const float4*)bias)[lane];
        float4 o;
        o.x = fmaxf(acc.x * 0.25f + b.x, 0.f);
        o.y = fmaxf(acc.y * 0.25f + b.y, 0.f);
        o.z = fmaxf(acc.z * 0.25f + b.z, 0.f);
        o.w = fmaxf(acc.w * 0.25f + b.w, 0.f);
        ((float4*)out)[(size_t)node * 8 + lane] = o;
    }
}

// ---------------- launch ----------------
extern "C" void kernel_launch(void* const* d_in, const int* in_sizes, int n_in,
                              void* d_out, int out_size)
{
    const float* x     = (const float*)d_in[0];
    const int*   ei    = (const int*)d_in[1];
    const float* W     = (const float*)d_in[2];
    const float* att_s = (const float*)d_in[3];
    const float* att_d = (const float*)d_in[4];
    const float* bias  = (const float*)d_in[5];
    float* out = (float*)d_out;

    int n = in_sizes[0] / HC;   // 100000
    int e = in_sizes[1] / 2;    // 1600000

    int totalBlocks = (n + 31) / 32;          // 3125
    int pa = (totalBlocks + 1) / 2;           // 1563 -> rows [0, pa*32)
    int pb = totalBlocks - pa;                // 1562
    int rowBase = pa * 32;
    const int AUX = 256;

    cudaFuncSetAttribute(k_pA, cudaFuncAttributeMaxDynamicSharedMemorySize, 81920);
    cudaFuncSetAttribute(k_pB, cudaFuncAttributeMaxDynamicSharedMemorySize, 81920);

    k_zero<<<(n + 255) / 256, 256>>>(n);

    k_pA<<<AUX + pa, 256, 81920>>>(x, W, att_s, att_d, ei, e, AUX);

    int nchunks = (n + 1023) / 1024;
    k_scan1<<<nchunks, 1024>>>(n);
    k_scan2<<<1, 128>>>(nchunks, n);
    k_scan3<<<nchunks, 1024>>>(n);

    k_pB<<<AUX + pb, 256, 81920>>>(x, W, att_s, att_d, ei, e, AUX, rowBase);

    k_main<<<(n * 32 + 255) / 256, 256>>>(bias, out, n);
}

// round 7
// speedup vs baseline: 1.2814x; 1.0665x over previous
#include <cuda_runtime.h>
#include <stdint.h>

#define HC    128
#define HEADS 4
#define NEG   0.2f
#define NMAX  100000
#define EMAX  1600000

typedef unsigned int u32;
typedef unsigned long long u64;

// ---------------- scratch ----------------
__device__ float g_h[NMAX * HC];
__device__ float g_asrc[NMAX * HEADS];
__device__ float g_adst[NMAX * HEADS];
__device__ int   g_deg[NMAX];          // zero-init; re-zeroed by k_main tail each call
__device__ int   g_offs[NMAX + 1];
__device__ int   g_cursor[NMAX];
__device__ int   g_csr[EMAX];
__device__ int   g_part[128];

// ---------------- packed f32x2 helpers ----------------
__device__ __forceinline__ u64 ffma2(u64 a, u64 b, u64 c) {
    u64 d;
    asm("fma.rn.f32x2 %0, %1, %2, %3;" : "=l"(d) : "l"(a), "l"(b), "l"(c));
    return d;
}
__device__ __forceinline__ u64 dup2(float v) {
    u64 d; unsigned r = __float_as_uint(v);
    asm("mov.b64 %0, {%1, %1};" : "=l"(d) : "r"(r));
    return d;
}
__device__ __forceinline__ void unpack2(u64 v, float& lo, float& hi) {
    unsigned a, b;
    asm("mov.b64 {%0, %1}, %2;" : "=r"(a), "=r"(b) : "l"(v));
    lo = __uint_as_float(a); hi = __uint_as_float(b);
}

// smem layout for k_proj (bytes):
//   [0,      65536)  W as u64 pairs   (8192 u64)  Wp[k*64 + cp] = (W[k][2cp], W[k][2cp+1])
//   [65536, 99328)   x stage f32 [64][132] padded
//   [99328, 100352)  att: [0..127]=att_s, [128..255]=att_d
#define SMP_X    65536
#define SMP_ATT  99328
#define SMP_TOT  100352

// ---------------- k_count ----------------
__global__ void k_count(const int* __restrict__ ei, int e)
{
    int tid = threadIdx.x;
    int nt = gridDim.x * 256;
    if ((e & 3) == 0) {
        const int4* d4 = (const int4*)(ei + e);
        int e4 = e >> 2;
        for (int i = blockIdx.x * 256 + tid; i < e4; i += nt) {
            int4 v = d4[i];
            atomicAdd(&g_deg[v.x], 1);
            atomicAdd(&g_deg[v.y], 1);
            atomicAdd(&g_deg[v.z], 1);
            atomicAdd(&g_deg[v.w], 1);
        }
    } else {
        for (int i = blockIdx.x * 256 + tid; i < e; i += nt)
            atomicAdd(&g_deg[ei[e + i]], 1);
    }
}

// ---------------- scans ----------------
__global__ void k_scan1(int n) {
    __shared__ int s[1024];
    int tid = threadIdx.x;
    int i = blockIdx.x * 1024 + tid;
    int v = (i < n) ? g_deg[i] : 0;
    s[tid] = v;
    __syncthreads();
    #pragma unroll
    for (int off = 1; off < 1024; off <<= 1) {
        int t2 = (tid >= off) ? s[tid - off] : 0;
        __syncthreads();
        s[tid] += t2;
        __syncthreads();
    }
    if (i < n) g_offs[i] = s[tid] - v;
    if (tid == 1023) g_part[blockIdx.x] = s[1023];
}

__global__ void k_scan3b(int n, int nchunks) {
    __shared__ int s[128];
    int t = threadIdx.x;
    if (t < 128) s[t] = (t < nchunks) ? g_part[t] : 0;
    __syncthreads();
    for (int off = 1; off < 128; off <<= 1) {
        int u = (t < 128 && t >= off) ? s[t - off] : 0;
        __syncthreads();
        if (t < 128) s[t] += u;
        __syncthreads();
    }
    int base = (blockIdx.x == 0) ? 0 : s[blockIdx.x - 1];
    int i = blockIdx.x * 1024 + t;
    if (i < n) {
        int v = g_offs[i] + base;
        g_offs[i] = v;
        g_cursor[i] = v;
    }
    if (blockIdx.x == 0 && t == 0) g_offs[n] = s[nchunks - 1];
}

// ---------------- k_proj: 64 rows/block, thread = 4 rows x 8 cols (f32x2); aux blocks scatter ----------------
__global__ void __launch_bounds__(256, 2) k_proj(
    const float* __restrict__ x, const float* __restrict__ W,
    const float* __restrict__ att_s, const float* __restrict__ att_d,
    const int* __restrict__ ei, int e, int aux, int n)
{
    extern __shared__ char sm[];
    int tid = threadIdx.x;

    if ((int)blockIdx.x < aux) {
        int nt = aux * 256;
        if ((e & 3) == 0) {
            const int4* s4 = (const int4*)ei;
            const int4* d4 = (const int4*)(ei + e);
            int e4 = e >> 2;
            for (int i = blockIdx.x * 256 + tid; i < e4; i += nt) {
                int4 sv = s4[i];
                int4 dv = d4[i];
                g_csr[atomicAdd(&g_cursor[dv.x], 1)] = sv.x;
                g_csr[atomicAdd(&g_cursor[dv.y], 1)] = sv.y;
                g_csr[atomicAdd(&g_cursor[dv.z], 1)] = sv.z;
                g_csr[atomicAdd(&g_cursor[dv.w], 1)] = sv.w;
            }
        } else {
            for (int i = blockIdx.x * 256 + tid; i < e; i += nt)
                g_csr[atomicAdd(&g_cursor[ei[e + i]], 1)] = ei[i];
        }
        return;
    }

    int row0 = (blockIdx.x - aux) * 64;

    // stage W (verbatim copy: row-major f32 pairs ARE the u64 operands)
    {
        const float4* Wg = (const float4*)W;
        float4* Ws = (float4*)sm;
        #pragma unroll
        for (int i = tid; i < 4096; i += 256) Ws[i] = Wg[i];
    }
    // stage att
    {
        float* attp = (float*)(sm + SMP_ATT);
        attp[tid] = (tid < 128) ? att_s[tid] : att_d[tid - 128];
    }
    // stage x tile [64][132]
    {
        float* xps = (float*)(sm + SMP_X);
        float4 z = make_float4(0.f, 0.f, 0.f, 0.f);
        #pragma unroll
        for (int i = tid; i < 2048; i += 256) {
            int r = i >> 5, c4 = i & 31;
            int grow = row0 + r;
            float4 v = (grow < n) ? ((const float4*)(x + (size_t)grow * HC))[c4] : z;
            *(float4*)(xps + r * 132 + c4 * 4) = v;
        }
    }
    __syncthreads();

    int cg = tid & 15;          // column group: cols {2cg, 2cg+1} + 32*j, j=0..3 (j == head)
    int rg = tid >> 4;          // row group: rows rg*4 .. rg*4+3

    const u64*   Wp = (const u64*)sm;
    const float* xp = (const float*)(sm + SMP_X) + rg * 4 * 132;
    const float* attp = (const float*)(sm + SMP_ATT);

    u64 A[4][4];
    #pragma unroll
    for (int r = 0; r < 4; r++)
        #pragma unroll
        for (int j = 0; j < 4; j++) A[r][j] = 0ull;

    #pragma unroll 4
    for (int k = 0; k < 128; k++) {
        u64 w0 = Wp[k * 64 + cg];
        u64 w1 = Wp[k * 64 + cg + 16];
        u64 w2 = Wp[k * 64 + cg + 32];
        u64 w3 = Wp[k * 64 + cg + 48];
        u64 x0 = dup2(xp[k]);
        u64 x1 = dup2(xp[k + 132]);
        u64 x2 = dup2(xp[k + 264]);
        u64 x3 = dup2(xp[k + 396]);
        A[0][0] = ffma2(w0, x0, A[0][0]);
        A[0][1] = ffma2(w1, x0, A[0][1]);
        A[0][2] = ffma2(w2, x0, A[0][2]);
        A[0][3] = ffma2(w3, x0, A[0][3]);
        A[1][0] = ffma2(w0, x1, A[1][0]);
        A[1][1] = ffma2(w1, x1, A[1][1]);
        A[1][2] = ffma2(w2, x1, A[1][2]);
        A[1][3] = ffma2(w3, x1, A[1][3]);
        A[2][0] = ffma2(w0, x2, A[2][0]);
        A[2][1] = ffma2(w1, x2, A[2][1]);
        A[2][2] = ffma2(w2, x2, A[2][2]);
        A[2][3] = ffma2(w3, x2, A[2][3]);
        A[3][0] = ffma2(w0, x3, A[3][0]);
        A[3][1] = ffma2(w1, x3, A[3][1]);
        A[3][2] = ffma2(w2, x3, A[3][2]);
        A[3][3] = ffma2(w3, x3, A[3][3]);
    }

    // epilogue: store h (coalesced 8B lanes -> 128B segments), compute att dots
    #pragma unroll
    for (int r = 0; r < 4; r++) {
        int row = row0 + rg * 4 + r;
        bool ok = (row < n);
        float ds[4], dd[4];
        #pragma unroll
        for (int j = 0; j < 4; j++) {
            u64 v = A[r][j];
            if (ok) *(u64*)(g_h + (size_t)row * HC + 32 * j + 2 * cg) = v;
            float a, b;
            unpack2(v, a, b);
            int c = 32 * j + 2 * cg;
            ds[j] = a * attp[c] + b * attp[c + 1];
            dd[j] = a * attp[128 + c] + b * attp[128 + c + 1];
        }
        #pragma unroll
        for (int off = 8; off >= 1; off >>= 1) {
            #pragma unroll
            for (int j = 0; j < 4; j++) {
                ds[j] += __shfl_xor_sync(0xffffffffu, ds[j], off);
                dd[j] += __shfl_xor_sync(0xffffffffu, dd[j], off);
            }
        }
        if (cg == 0 && ok) {
            #pragma unroll
            for (int j = 0; j < 4; j++) {
                g_asrc[row * HEADS + j] = ds[j];
                g_adst[row * HEADS + j] = dd[j];
            }
        }
    }
}

// ---------------- k_main: one warp per dst node, no-max softmax, unroll 4 ----------------
__global__ void k_main(const float* __restrict__ bias, float* __restrict__ out, int n)
{
    int gt = blockIdx.x * blockDim.x + threadIdx.x;
    if (gt < n) g_deg[gt] = 0;          // reset for next call (not read here)

    int node = gt >> 5;
    if (node >= n) return;
    int lane = threadIdx.x & 31;
    int head = lane >> 3;

    float adst = g_adst[node * HEADS + head];
    float s = 0.f;
    float4 acc = make_float4(0.f, 0.f, 0.f, 0.f);

    int beg = g_offs[node];
    int end = g_offs[node + 1];
    const float4* h4 = (const float4*)g_h;

    int i = beg;
    for (; i + 4 <= end; i += 4) {
        int s0 = g_csr[i], s1 = g_csr[i + 1], s2 = g_csr[i + 2], s3 = g_csr[i + 3];
        float e0 = g_asrc[s0 * HEADS + head] + adst;
        float e1 = g_asrc[s1 * HEADS + head] + adst;
        float e2 = g_asrc[s2 * HEADS + head] + adst;
        float e3 = g_asrc[s3 * HEADS + head] + adst;
        e0 = (e0 > 0.f) ? e0 : NEG * e0;
        e1 = (e1 > 0.f) ? e1 : NEG * e1;
        e2 = (e2 > 0.f) ? e2 : NEG * e2;
        e3 = (e3 > 0.f) ? e3 : NEG * e3;
        float4 h0 = h4[(size_t)s0 * 32 + lane];
        float4 h1 = h4[(size_t)s1 * 32 + lane];
        float4 h2 = h4[(size_t)s2 * 32 + lane];
        float4 h3 = h4[(size_t)s3 * 32 + lane];
        float p0 = __expf(e0), p1 = __expf(e1), p2 = __expf(e2), p3 = __expf(e3);
        s += (p0 + p1) + (p2 + p3);
        acc.x = fmaf(p0, h0.x, fmaf(p1, h1.x, fmaf(p2, h2.x, fmaf(p3, h3.x, acc.x))));
        acc.y = fmaf(p0, h0.y, fmaf(p1, h1.y, fmaf(p2, h2.y, fmaf(p3, h3.y, acc.y))));
        acc.z = fmaf(p0, h0.z, fmaf(p1, h1.z, fmaf(p2, h2.z, fmaf(p3, h3.z, acc.z))));
        acc.w = fmaf(p0, h0.w, fmaf(p1, h1.w, fmaf(p2, h2.w, fmaf(p3, h3.w, acc.w))));
    }
    for (; i < end; i++) {
        int s0 = g_csr[i];
        float e0 = g_asrc[s0 * HEADS + head] + adst;
        e0 = (e0 > 0.f) ? e0 : NEG * e0;
        float4 h0 = h4[(size_t)s0 * 32 + lane];
        float p0 = __expf(e0);
        s += p0;
        acc.x = fmaf(p0, h0.x, acc.x);
        acc.y = fmaf(p0, h0.y, acc.y);
        acc.z = fmaf(p0, h0.z, acc.z);
        acc.w = fmaf(p0, h0.w, acc.w);
    }
    {   // self loop
        float e0 = g_asrc[node * HEADS + head] + adst;
        e0 = (e0 > 0.f) ? e0 : NEG * e0;
        float4 h0 = h4[(size_t)node * 32 + lane];
        float p0 = __expf(e0);
        s += p0;
        acc.x = fmaf(p0, h0.x, acc.x);
        acc.y = fmaf(p0, h0.y, acc.y);
        acc.z = fmaf(p0, h0.z, acc.z);
        acc.w = fmaf(p0, h0.w, acc.w);
    }

    float inv = 1.f / (s + 1e-16f);
    acc.x *= inv; acc.y *= inv; acc.z *= inv; acc.w *= inv;

    #pragma unroll
    for (int off = 8; off <= 16; off <<= 1) {
        acc.x += __shfl_xor_sync(0xffffffffu, acc.x, off);
        acc.y += __shfl_xor_sync(0xffffffffu, acc.y, off);
        acc.z += __shfl_xor_sync(0xffffffffu, acc.z, off);
        acc.w += __shfl_xor_sync(0xffffffffu, acc.w, off);
    }

    if (lane < 8) {
        float4 b = ((const float4*)bias)[lane];
        float4 o;
        o.x = fmaxf(acc.x * 0.25f + b.x, 0.f);
        o.y = fmaxf(acc.y * 0.25f + b.y, 0.f);
        o.z = fmaxf(acc.z * 0.25f + b.z, 0.f);
        o.w = fmaxf(acc.w * 0.25f + b.w, 0.f);
        ((float4*)out)[(size_t)node * 8 + lane] = o;
    }
}

// ---------------- launch ----------------
extern "C" void kernel_launch(void* const* d_in, const int* in_sizes, int n_in,
                              void* d_out, int out_size)
{
    const float* x     = (const float*)d_in[0];
    const int*   ei    = (const int*)d_in[1];
    const float* W     = (const float*)d_in[2];
    const float* att_s = (const float*)d_in[3];
    const float* att_d = (const float*)d_in[4];
    const float* bias  = (const float*)d_in[5];
    float* out = (float*)d_out;

    int n = in_sizes[0] / HC;   // 100000
    int e = in_sizes[1] / 2;    // 1600000

    cudaFuncSetAttribute(k_proj, cudaFuncAttributeMaxDynamicSharedMemorySize, SMP_TOT);

    k_count<<<256, 256>>>(ei, e);

    int nchunks = (n + 1023) / 1024;
    k_scan1<<<nchunks, 1024>>>(n);
    k_scan3b<<<nchunks, 1024>>>(n, nchunks);

    int ntiles = (n + 63) / 64;
    const int AUX = 64;
    k_proj<<<AUX + ntiles, 256, SMP_TOT>>>(x, W, att_s, att_d, ei, e, AUX, n);

    k_main<<<(n * 32 + 255) / 256, 256>>>(bias, out, n);
}